// round 1
// baseline (speedup 1.0000x reference)
#include <cuda_runtime.h>

#define FULL 0xffffffffu

constexpr int WARPS_PER_BLOCK = 8;

__device__ __forceinline__ float warpSum(float v) {
    v += __shfl_xor_sync(FULL, v, 16);
    v += __shfl_xor_sync(FULL, v, 8);
    v += __shfl_xor_sync(FULL, v, 4);
    v += __shfl_xor_sync(FULL, v, 2);
    v += __shfl_xor_sync(FULL, v, 1);
    return v;
}
__device__ __forceinline__ float warpMin(float v) {
    #pragma unroll
    for (int o = 16; o > 0; o >>= 1) v = fminf(v, __shfl_xor_sync(FULL, v, o));
    return v;
}
__device__ __forceinline__ float warpMax(float v) {
    #pragma unroll
    for (int o = 16; o > 0; o >>= 1) v = fmaxf(v, __shfl_xor_sync(FULL, v, o));
    return v;
}

// One warp per molecule:
//   1) Gram C = G G^T (32x32) via register/shuffle outer products
//   2) Householder tridiagonalization in shared memory (row-per-lane)
//   3) Smallest eigenvalue via warp-parallel Sturm bisection (32 probes/round)
__global__ __launch_bounds__(256) void corr_eig_kernel(
    const float* __restrict__ sr, float* __restrict__ out, int M)
{
    __shared__ float shA[WARPS_PER_BLOCK][32 * 33];   // padded 32x33 per warp
    __shared__ float shV[WARPS_PER_BLOCK][32];
    __shared__ float shW[WARPS_PER_BLOCK][32];
    __shared__ float shD[WARPS_PER_BLOCK][32];
    __shared__ float shE[WARPS_PER_BLOCK][32];

    const int w    = threadIdx.x >> 5;
    const int lane = threadIdx.x & 31;
    const int mol  = blockIdx.x * WARPS_PER_BLOCK + w;
    if (mol >= M) return;

    float* A = shA[w];
    float* V = shV[w];
    float* W = shW[w];
    float* D = shD[w];
    float* E = shE[w];

    // ---------------- Phase 1: Gram (lane holds row `lane` of C) ----------------
    float a[32];
    #pragma unroll
    for (int j = 0; j < 32; j++) a[j] = 0.f;

    // G row for this lane: 128 floats = 32 float4
    const float4* g = reinterpret_cast<const float4*>(sr) + ((size_t)mol * 32 + lane) * 32;

    #pragma unroll 1
    for (int c = 0; c < 32; c++) {
        float4 x = g[c];
        #pragma unroll
        for (int j = 0; j < 32; j++) {
            float t;
            t  = __shfl_sync(FULL, x.x, j) * x.x;
            t += __shfl_sync(FULL, x.y, j) * x.y;
            t += __shfl_sync(FULL, x.z, j) * x.z;
            t += __shfl_sync(FULL, x.w, j) * x.w;
            a[j] += t;
        }
    }

    #pragma unroll
    for (int j = 0; j < 32; j++) A[lane * 33 + j] = a[j];
    __syncwarp();

    // ---------------- Phase 2: Householder tridiagonalization ----------------
    // Lane i owns row i of A. Rows <= current k may hold stale values; they are
    // never read again (V[j]=0 for j<=k kills their contributions).
    #pragma unroll 1
    for (int k = 0; k < 30; k++) {
        float xk  = A[lane * 33 + k];          // A[lane][k] (column k via symmetry)
        bool  act = (lane > k);
        float sigma = warpSum(act ? xk * xk : 0.f);
        float x1 = __shfl_sync(FULL, xk, k + 1);   // A[k+1][k]
        float dk = __shfl_sync(FULL, xk, k);       // A[k][k]

        float alpha = -copysignf(sqrtf(sigma), x1);
        float beta, ek;
        if (sigma > 1e-20f) {
            beta = 1.0f / (sigma - alpha * x1);    // = 2 / v^T v  (always > 0)
            ek = alpha;
        } else {
            beta = 0.f;                             // skip reflection
            ek = x1;
            alpha = x1;                             // so v_{k+1} = 0
        }
        if (lane == 0) { D[k] = dk; E[k] = ek; }

        float v = act ? xk : 0.f;
        if (lane == k + 1) v = x1 - alpha;
        V[lane] = v;
        __syncwarp();

        // p = beta * A v   (trailing block only)
        float p = 0.f;
        for (int j = k + 1; j < 32; j++) p += A[lane * 33 + j] * V[j];
        p *= beta;

        float s  = warpSum(p * v);                  // p^T v
        float wv = p - 0.5f * beta * s * v;
        W[lane] = wv;
        __syncwarp();

        // A <- A - v w^T - w v^T  (only active rows written)
        if (act) {
            for (int j = k + 1; j < 32; j++)
                A[lane * 33 + j] -= v * W[j] + wv * V[j];
        }
        __syncwarp();
    }
    if (lane == 0) {
        D[30] = A[30 * 33 + 30];
        E[30] = A[31 * 33 + 30];
        D[31] = A[31 * 33 + 31];
    }
    __syncwarp();

    // ---------------- Phase 3: smallest eigenvalue via Sturm bisection ----------------
    // Gershgorin bounds
    {
        float di = D[lane];
        float el = (lane > 0)  ? E[lane - 1] : 0.f;
        float er = (lane < 31) ? E[lane]     : 0.f;
        float rad = fabsf(el) + fabsf(er);
        float lo = warpMin(di - rad);
        float hi = warpMax(di + rad);

        #pragma unroll 1
        for (int r = 0; r < 6; r++) {
            float h = (hi - lo) * (1.0f / 33.0f);
            float x = lo + h * (float)(lane + 1);

            // Sturm count: #eigenvalues < x
            float q = D[0] - x;
            int cnt = (q < 0.f) ? 1 : 0;
            #pragma unroll
            for (int i = 1; i < 32; i++) {
                float e2 = E[i - 1];
                e2 *= e2;
                float qn = (D[i] - x) - __fdividef(e2, q);
                if (qn == 0.f) qn = -1e-30f;
                cnt += (qn < 0.f) ? 1 : 0;
                q = qn;
            }

            unsigned mask = __ballot_sync(FULL, cnt >= 1);
            int j0 = (mask == 0u) ? 32 : (__ffs(mask) - 1);
            // lambda_min in (lo + j0*h, lo + (j0+1)*h]
            lo = lo + h * (float)j0;
            hi = lo + h;
        }

        if (lane == 0) out[mol] = 0.5f * (lo + hi);
    }
}

extern "C" void kernel_launch(void* const* d_in, const int* in_sizes, int n_in,
                              void* d_out, int out_size) {
    const float* sr = (const float*)d_in[0];
    // d_in[1] (idx_m) unused: groups are uniform [M, 32, 128]
    float* out = (float*)d_out;
    int M = in_sizes[0] >> 12;   // / (32*128)

    int blocks = (M + WARPS_PER_BLOCK - 1) / WARPS_PER_BLOCK;
    corr_eig_kernel<<<blocks, 256>>>(sr, out, M);
}

// round 2
// speedup vs baseline: 1.3909x; 1.3909x over previous
#include <cuda_runtime.h>
#include <cstdint>

#define FULL 0xffffffffu

constexpr int WPB = 4;   // warps per block

#define FMA_F32X2(out, a, b, c) \
    asm("fma.rn.f32x2 %0, %1, %2, %3;" : "=l"(out) : "l"(a), "l"(b), "l"(c))

__device__ __forceinline__ float warpSum(float v) {
    v += __shfl_xor_sync(FULL, v, 16);
    v += __shfl_xor_sync(FULL, v, 8);
    v += __shfl_xor_sync(FULL, v, 4);
    v += __shfl_xor_sync(FULL, v, 2);
    v += __shfl_xor_sync(FULL, v, 1);
    return v;
}
__device__ __forceinline__ float warpMin(float v) {
    #pragma unroll
    for (int o = 16; o > 0; o >>= 1) v = fminf(v, __shfl_xor_sync(FULL, v, o));
    return v;
}

// One warp per molecule.
// Phase 1: Gram C = G G^T via shared-broadcast LDS.128 + packed f32x2 FMA.
//          Lane l accumulates row l of C in registers a[32].
// Phase 2: Householder tridiagonalization, A fully register-resident
//          (row-per-lane, k-loop fully unrolled). (v,w) staged as float2 in
//          shared; V broadcast via shuffle in the dot pass.
// Phase 3: lambda_min via warp-parallel Sturm bisection on [0, min diag(T)].
__global__ __launch_bounds__(128) void corr_eig_kernel(
    const float* __restrict__ sr, float* __restrict__ out, int M)
{
    __shared__ float  shG[WPB][32 * 36];   // 36-float row stride: 16B-aligned rows
    __shared__ float2 shVW[WPB][32];

    const int w    = threadIdx.x >> 5;
    const int lane = threadIdx.x & 31;
    const int mol  = blockIdx.x * WPB + w;
    if (mol >= M) return;

    float*  G  = shG[w];
    float2* VW = shVW[w];

    // ---------------- Phase 1: Gram ----------------
    float a[32];
    #pragma unroll
    for (int j = 0; j < 32; j++) a[j] = 0.f;

    // Own row: 128 floats = 32 x ulonglong2 (each = 2 f32x2 pairs)
    const ulonglong2* g2 =
        reinterpret_cast<const ulonglong2*>(sr) + ((size_t)mol * 32 + lane) * 32;

    #pragma unroll 1
    for (int c = 0; c < 4; c++) {
        ulonglong2 xv[8];                      // own 32-feat chunk
        #pragma unroll
        for (int i = 0; i < 8; i++) xv[i] = g2[c * 8 + i];

        __syncwarp();
        #pragma unroll
        for (int i = 0; i < 8; i++)
            *reinterpret_cast<ulonglong2*>(&G[lane * 36 + 4 * i]) = xv[i];
        __syncwarp();

        #pragma unroll 4
        for (int j = 0; j < 32; j++) {
            unsigned long long acc = 0ull;     // two fp32 accumulators packed
            #pragma unroll
            for (int i = 0; i < 8; i++) {
                ulonglong2 y = *reinterpret_cast<const ulonglong2*>(&G[j * 36 + 4 * i]);
                FMA_F32X2(acc, xv[i].x, y.x, acc);
                FMA_F32X2(acc, xv[i].y, y.y, acc);
            }
            float s0, s1;
            asm("mov.b64 {%0,%1}, %2;" : "=f"(s0), "=f"(s1) : "l"(acc));
            a[j] += s0 + s1;
        }
    }

    // ---------------- Phase 2: Householder tridiagonalization ----------------
    // Lane i owns row i of A in registers. Inactive lanes (lane <= k) have
    // v = w = 0, so their rows freeze and their (finite) stale values never
    // contaminate active lanes.
    float d_reg = 0.f, e_reg = 0.f;

    #pragma unroll
    for (int k = 0; k < 30; k++) {
        const bool act = (lane > k);
        float xk = a[k];                                   // column k (symmetry)
        float sigma = warpSum(act ? xk * xk : 0.f);
        float x1 = __shfl_sync(FULL, xk, k + 1);           // A[k+1][k]
        float alpha = -copysignf(sqrtf(sigma), x1);
        bool  ok   = (sigma > 1e-20f);
        float beta = ok ? 1.0f / (sigma - alpha * x1) : 0.f;  // 2 / v^T v
        float ek   = ok ? alpha : x1;
        if (lane == k) { d_reg = xk; e_reg = ek; }

        float v = act ? xk : 0.f;
        if (lane == k + 1) v = ok ? (x1 - alpha) : 0.f;

        // p = beta * (A v) restricted to trailing block; V broadcast via shfl
        float p = 0.f;
        #pragma unroll
        for (int j = k + 1; j < 32; j++)
            p += a[j] * __shfl_sync(FULL, v, j);
        p = act ? p * beta : 0.f;

        float s  = warpSum(p * v);                         // p^T v
        float wv = p - (0.5f * beta * s) * v;              // 0 on inactive lanes

        VW[lane] = make_float2(v, wv);
        __syncwarp();

        // A <- A - v w^T - w v^T   (one broadcast LDS.64 per column)
        #pragma unroll
        for (int j = k + 1; j < 32; j++) {
            float2 t = VW[j];
            a[j] -= v * t.y + wv * t.x;
        }
        __syncwarp();
    }
    if (lane == 30) { d_reg = a[30]; e_reg = a[31]; }
    if (lane == 31) { d_reg = a[31]; e_reg = 0.f; }

    // ---------------- Phase 3: Sturm bisection ----------------
    // C is PSD => lambda_min in [0, min_i T_ii] (eigenvalue interlacing).
    float e2 = e_reg * e_reg;
    float lo = 0.f;
    float hi = warpMin(d_reg) * 1.0001f;

    #pragma unroll 1
    for (int r = 0; r < 5; r++) {
        float h = (hi - lo) * (1.0f / 33.0f);
        float x = fmaf(h, (float)(lane + 1), lo);

        float q  = __shfl_sync(FULL, d_reg, 0) - x;
        int cnt  = (q < 0.f);
        #pragma unroll
        for (int i = 1; i < 32; i++) {
            float ei2 = __shfl_sync(FULL, e2, i - 1);
            float qn  = (__shfl_sync(FULL, d_reg, i) - x) - __fdividef(ei2, q);
            if (qn == 0.f) qn = -1e-30f;
            cnt += (qn < 0.f);
            q = qn;
        }
        unsigned mask = __ballot_sync(FULL, cnt >= 1);
        int j0 = mask ? (__ffs(mask) - 1) : 32;
        lo += h * (float)j0;
        hi  = lo + h;
    }

    if (lane == 0) out[mol] = 0.5f * (lo + hi);
}

extern "C" void kernel_launch(void* const* d_in, const int* in_sizes, int n_in,
                              void* d_out, int out_size) {
    const float* sr = (const float*)d_in[0];
    // d_in[1] (idx_m) unused: uniform groups -> [M, 32, 128]
    float* out = (float*)d_out;
    int M = in_sizes[0] >> 12;   // / (32*128)

    int blocks = (M + WPB - 1) / WPB;
    corr_eig_kernel<<<blocks, 128>>>(sr, out, M);
}

// round 3
// speedup vs baseline: 1.5320x; 1.1015x over previous
#include <cuda_runtime.h>
#include <cstdint>

#define FULL 0xffffffffu

constexpr int WPB = 4;   // warps per block

#define FMA_F32X2(out, a, b, c) \
    asm("fma.rn.f32x2 %0, %1, %2, %3;" : "=l"(out) : "l"(a), "l"(b), "l"(c))

__device__ __forceinline__ float warpSum(float v) {
    v += __shfl_xor_sync(FULL, v, 16);
    v += __shfl_xor_sync(FULL, v, 8);
    v += __shfl_xor_sync(FULL, v, 4);
    v += __shfl_xor_sync(FULL, v, 2);
    v += __shfl_xor_sync(FULL, v, 1);
    return v;
}
__device__ __forceinline__ float warpMin(float v) {
    #pragma unroll
    for (int o = 16; o > 0; o >>= 1) v = fminf(v, __shfl_xor_sync(FULL, v, o));
    return v;
}

// One warp per molecule.
// Phase 1: Gram C = G G^T via shared-broadcast LDS.128 + packed f32x2 FMA.
// Phase 2: Householder tridiag; A register-resident (row-per-lane, full unroll);
//          sigma computed locally on lane k (1 shfl instead of warpSum);
//          V/W consumed via broadcast LDS.128 (4 elems/op).
// Phase 3: Sturm bisection; (d,e^2) in shared, read via LDS.128; 4 rounds.
__global__ __launch_bounds__(128) void corr_eig_kernel(
    const float* __restrict__ sr, float* __restrict__ out, int M)
{
    __shared__ float  shG[WPB][32 * 36];   // padded rows, 16B aligned
    __shared__ float  shV[WPB][32];
    __shared__ float  shW[WPB][32];
    __shared__ float2 shDE[WPB][32];

    const int w    = threadIdx.x >> 5;
    const int lane = threadIdx.x & 31;
    const int mol  = blockIdx.x * WPB + w;
    if (mol >= M) return;

    float* G  = shG[w];
    float* sV = shV[w];
    float* sW = shW[w];

    // ---------------- Phase 1: Gram ----------------
    float a[32];
    #pragma unroll
    for (int j = 0; j < 32; j++) a[j] = 0.f;

    const ulonglong2* g2 =
        reinterpret_cast<const ulonglong2*>(sr) + ((size_t)mol * 32 + lane) * 32;

    #pragma unroll 1
    for (int c = 0; c < 4; c++) {
        ulonglong2 xv[8];                      // own 32-feat chunk
        #pragma unroll
        for (int i = 0; i < 8; i++) xv[i] = g2[c * 8 + i];

        __syncwarp();
        #pragma unroll
        for (int i = 0; i < 8; i++)
            *reinterpret_cast<ulonglong2*>(&G[lane * 36 + 4 * i]) = xv[i];
        __syncwarp();

        #pragma unroll 4
        for (int j = 0; j < 32; j++) {
            unsigned long long acc = 0ull;     // two packed fp32 accumulators
            #pragma unroll
            for (int i = 0; i < 8; i++) {
                ulonglong2 y = *reinterpret_cast<const ulonglong2*>(&G[j * 36 + 4 * i]);
                FMA_F32X2(acc, xv[i].x, y.x, acc);
                FMA_F32X2(acc, xv[i].y, y.y, acc);
            }
            float s0, s1;
            asm("mov.b64 {%0,%1}, %2;" : "=f"(s0), "=f"(s1) : "l"(acc));
            a[j] += s0 + s1;
        }
    }

    // ---------------- Phase 2: Householder tridiagonalization ----------------
    // Lane i owns row i. Inactive lanes (lane <= k) have v = w = 0: their rows
    // freeze and never contaminate active lanes. sV/sW entries for j <= k are 0,
    // so aligned LDS.128 over-reads are harmless.
    float d_reg = 0.f, e_reg = 0.f;

    #pragma unroll
    for (int k = 0; k < 30; k++) {
        const bool act = (lane > k);

        // Trailing norm of OWN row (only lane k's value is used)
        float sig_loc = 0.f;
        #pragma unroll
        for (int j = k + 1; j < 32; j++) sig_loc = fmaf(a[j], a[j], sig_loc);
        float sigma = __shfl_sync(FULL, sig_loc, k);
        float x1    = __shfl_sync(FULL, a[k + 1], k);   // A[k][k+1]

        float alpha = -copysignf(sqrtf(sigma), x1);
        bool  ok    = (sigma > 1e-20f);
        float beta  = ok ? 1.0f / (sigma - alpha * x1) : 0.f;   // 2 / v^T v
        if (lane == k) { d_reg = a[k]; e_reg = ok ? alpha : x1; }

        float v = act ? a[k] : 0.f;
        if (lane == k + 1) v = ok ? (x1 - alpha) : 0.f;

        __syncwarp();                     // prior iter's sV/sW reads done
        sV[lane] = v;
        __syncwarp();

        // p = beta * (A v), V read via broadcast LDS.128
        float p = 0.f;
        #pragma unroll
        for (int jq = (k + 1) >> 2; jq < 8; jq++) {
            float4 v4 = *reinterpret_cast<const float4*>(&sV[4 * jq]);
            p = fmaf(a[4 * jq + 0], v4.x, p);
            p = fmaf(a[4 * jq + 1], v4.y, p);
            p = fmaf(a[4 * jq + 2], v4.z, p);
            p = fmaf(a[4 * jq + 3], v4.w, p);
        }
        p = act ? p * beta : 0.f;

        float s  = warpSum(p * v);                     // p^T v
        float wv = p - (0.5f * beta * s) * v;          // 0 on inactive lanes

        sW[lane] = wv;
        __syncwarp();

        // A <- A - v w^T - w v^T
        #pragma unroll
        for (int jq = (k + 1) >> 2; jq < 8; jq++) {
            float4 v4 = *reinterpret_cast<const float4*>(&sV[4 * jq]);
            float4 w4 = *reinterpret_cast<const float4*>(&sW[4 * jq]);
            a[4 * jq + 0] -= v * w4.x + wv * v4.x;
            a[4 * jq + 1] -= v * w4.y + wv * v4.y;
            a[4 * jq + 2] -= v * w4.z + wv * v4.z;
            a[4 * jq + 3] -= v * w4.w + wv * v4.w;
        }
    }
    if (lane == 30) { d_reg = a[30]; e_reg = a[31]; }
    if (lane == 31) { d_reg = a[31]; e_reg = 0.f; }

    // ---------------- Phase 3: Sturm bisection ----------------
    // C is PSD => lambda_min in [0, min_i T_ii].
    __syncwarp();
    shDE[w][lane] = make_float2(d_reg, e_reg * e_reg);
    __syncwarp();
    const float4* DE4 = reinterpret_cast<const float4*>(shDE[w]);  // (d,e2) pairs

    float lo = 0.f;
    float hi = warpMin(d_reg) * 1.0001f;

    #pragma unroll 1
    for (int r = 0; r < 4; r++) {
        float h = (hi - lo) * (1.0f / 33.0f);
        float x = fmaf(h, (float)(lane + 1), lo);

        float4 t = DE4[0];                       // d0, e2_0, d1, e2_1
        float q   = t.x - x;
        int   cnt = (q < 0.f);
        float eprev = t.y;
        {
            float qn = (t.z - x) - __fdividef(eprev, q);
            if (qn == 0.f) qn = -1e-30f;
            cnt += (qn < 0.f);
            q = qn; eprev = t.w;
        }
        #pragma unroll
        for (int m = 1; m < 16; m++) {
            t = DE4[m];
            float qn = (t.x - x) - __fdividef(eprev, q);
            if (qn == 0.f) qn = -1e-30f;
            cnt += (qn < 0.f);
            q = qn; eprev = t.y;

            qn = (t.z - x) - __fdividef(eprev, q);
            if (qn == 0.f) qn = -1e-30f;
            cnt += (qn < 0.f);
            q = qn; eprev = t.w;
        }

        unsigned mask = __ballot_sync(FULL, cnt >= 1);
        int j0 = mask ? (__ffs(mask) - 1) : 32;
        lo += h * (float)j0;
        hi  = lo + h;
    }

    if (lane == 0) out[mol] = 0.5f * (lo + hi);
}

extern "C" void kernel_launch(void* const* d_in, const int* in_sizes, int n_in,
                              void* d_out, int out_size) {
    const float* sr = (const float*)d_in[0];
    // d_in[1] (idx_m) unused: uniform groups -> [M, 32, 128]
    float* out = (float*)d_out;
    int M = in_sizes[0] >> 12;   // / (32*128)

    int blocks = (M + WPB - 1) / WPB;
    corr_eig_kernel<<<blocks, 128>>>(sr, out, M);
}